// round 16
// baseline (speedup 1.0000x reference)
#include <cuda_runtime.h>
#include <cuda_fp16.h>
#include <math.h>

// ---------------------------------------------------------------------------
// Problem constants
// ---------------------------------------------------------------------------
#define NB_GRAPHS 512          // B
#define M_NODES   64           // nodes per graph
#define EPG       512          // edges per graph

// ---------------------------------------------------------------------------
// Scratch layout (single __device__ array, no allocations)
// ---------------------------------------------------------------------------
#define SZ_F0 (32768*64)
#define SZ_F1 (32768*32)
#define SZ_F2 (32768*16)
#define SZ_H  (512*12288)
#define SZ_Y1 (512*256)
#define SZ_WT0 (12288*256)

#define OFF_FQ0 0
#define OFF_FC0 (OFF_FQ0 + SZ_F0)
#define OFF_FQ1 (OFF_FC0 + SZ_F0)
#define OFF_FC1 (OFF_FQ1 + SZ_F1)
#define OFF_FQ2 (OFF_FC1 + SZ_F1)
#define OFF_FC2 (OFF_FQ2 + SZ_F2)
#define OFF_H   (OFF_FC2 + SZ_F2)
#define OFF_Y1  (OFF_H + SZ_H)
#define OFF_WT0 (OFF_Y1 + SZ_Y1)
#define SCRATCH_TOTAL (OFF_WT0 + SZ_WT0)

__device__ float g_scratch[SCRATCH_TOTAL];

// ---------------------------------------------------------------------------
// Helpers
// ---------------------------------------------------------------------------
typedef unsigned long long u64;

__device__ __forceinline__ unsigned f2tf32(float f) {
    unsigned u; asm("cvt.rna.tf32.f32 %0, %1;" : "=r"(u) : "f"(f)); return u;
}
__device__ __forceinline__ float tf32f(float f) {
    return __uint_as_float(f2tf32(f));
}
__device__ __forceinline__ void cp_async16(float* dst, const float* src) {
    unsigned d = (unsigned)__cvta_generic_to_shared(dst);
    asm volatile("cp.async.cg.shared.global [%0], [%1], 16;" :: "r"(d), "l"(src));
}
__device__ __forceinline__ void mma_tf32(float c[4],
    unsigned a0, unsigned a1, unsigned a2, unsigned a3,
    unsigned b0, unsigned b1)
{
    asm volatile(
        "mma.sync.aligned.m16n8k8.row.col.f32.tf32.tf32.f32 "
        "{%0,%1,%2,%3}, {%4,%5,%6,%7}, {%8,%9}, {%0,%1,%2,%3};"
        : "+f"(c[0]), "+f"(c[1]), "+f"(c[2]), "+f"(c[3])
        : "r"(a0), "r"(a1), "r"(a2), "r"(a3), "r"(b0), "r"(b1));
}
__device__ __forceinline__ void mma_f16(float c[4],
    unsigned a0, unsigned a1, unsigned a2, unsigned a3,
    unsigned b0, unsigned b1)
{
    asm volatile(
        "mma.sync.aligned.m16n8k16.row.col.f32.f16.f16.f32 "
        "{%0,%1,%2,%3}, {%4,%5,%6,%7}, {%8,%9}, {%0,%1,%2,%3};"
        : "+f"(c[0]), "+f"(c[1]), "+f"(c[2]), "+f"(c[3])
        : "r"(a0), "r"(a1), "r"(a2), "r"(a3), "r"(b0), "r"(b1));
}
__device__ __forceinline__ void ldsm_x4(unsigned& r0, unsigned& r1,
                                        unsigned& r2, unsigned& r3, unsigned addr)
{
    asm volatile("ldmatrix.sync.aligned.m8n8.x4.shared.b16 {%0,%1,%2,%3}, [%4];"
        : "=r"(r0), "=r"(r1), "=r"(r2), "=r"(r3) : "r"(addr));
}

// ---------------------------------------------------------------------------
// GCN layer body (float4-vectorized GEMM). Feature outputs tf32-rounded.
// ---------------------------------------------------------------------------
template<int FIN, int FOUT>
__device__ __forceinline__ void gcn_layer_body(
    const float* __restrict__ sx, float* __restrict__ sA, float* __restrict__ sout,
    const float* __restrict__ sdinv,
    const int* __restrict__ sstart, const int* __restrict__ ssrc,
    const float* __restrict__ W, const float* __restrict__ bias,
    float* __restrict__ outg, int t)
{
    {
        const int j = t % FOUT;
        float wcol[FIN];
        #pragma unroll
        for (int k = 0; k < FIN; ++k) wcol[k] = __ldg(&W[k*FOUT + j]);
        for (int i = t; i < 64*FOUT; i += 256) {
            int n = i / FOUT;
            const float4* xr = (const float4*)(sx + n*FIN);
            float acc = 0.f;
            #pragma unroll
            for (int k4 = 0; k4 < FIN/4; ++k4) {
                float4 xv = xr[k4];
                acc += xv.x*wcol[4*k4] + xv.y*wcol[4*k4+1]
                     + xv.z*wcol[4*k4+2] + xv.w*wcol[4*k4+3];
            }
            sA[i] = acc * sdinv[n];
        }
    }
    __syncthreads();

    {
        const int wp = t >> 5, lane = t & 31;
        constexpr int CH = (FOUT + 31) / 32;
        for (int d = wp; d < 64; d += 8) {
            const int e0 = sstart[d], e1 = sstart[d + 1];
            const float dv = sdinv[d];
            float a[CH];
            #pragma unroll
            for (int c = 0; c < CH; ++c) {
                int j = lane + 32*c;
                a[c] = (j < FOUT) ? sA[d*FOUT + j] : 0.f;
            }
            for (int e = e0; e < e1; ++e) {
                int s = ssrc[e];
                #pragma unroll
                for (int c = 0; c < CH; ++c) {
                    int j = lane + 32*c;
                    if (j < FOUT) a[c] += sA[s*FOUT + j];
                }
            }
            #pragma unroll
            for (int c = 0; c < CH; ++c) {
                int j = lane + 32*c;
                if (j < FOUT) sout[d*FOUT + j] = dv*a[c] + __ldg(&bias[j]);
            }
        }
    }
    __syncthreads();

    for (int i = t; i < 64*FOUT; i += 256)
        outg[i] = tf32f(sout[i]);           // tf32-rounded feature copies
}

// ---------------------------------------------------------------------------
// prep_all: [0,1024) GCN; [1024,1536) y1 bias init; [1536,4608) Wl0 tf32.
// ---------------------------------------------------------------------------
__global__ void __launch_bounds__(256) prep_all(
    const float* __restrict__ xq, const float* __restrict__ xc,
    const float* __restrict__ Wg0, const float* __restrict__ bg0,
    const float* __restrict__ Wg1, const float* __restrict__ bg1,
    const float* __restrict__ Wg2, const float* __restrict__ bg2,
    const int* __restrict__ srcq, const int* __restrict__ dstq,
    const int* __restrict__ srcc, const int* __restrict__ dstc,
    const float* __restrict__ bl0, const float* __restrict__ Wl0)
{
    __shared__ __align__(16) float pool[10240];
    __shared__ int   ssrc[EPG];
    __shared__ int   sstart[65];
    __shared__ int   scnt[64];
    __shared__ float sdinv[64];

    const int b = blockIdx.x;
    const int t = threadIdx.x;

    if (b >= 2*NB_GRAPHS) {
        if (b < 2*NB_GRAPHS + 512) {
            int i = (b - 2*NB_GRAPHS)*256 + t;
            g_scratch[OFF_Y1 + i] = __ldg(&bl0[i & 255]);
        } else {
            int i = (b - (2*NB_GRAPHS + 512))*256 + t;   // float4 index
            float4 v = ((const float4*)Wl0)[i];
            float4 o;
            o.x = tf32f(v.x); o.y = tf32f(v.y); o.z = tf32f(v.z); o.w = tf32f(v.w);
            ((float4*)(g_scratch + OFF_WT0))[i] = o;
        }
        return;
    }

    const bool isC = (b >= NB_GRAPHS);
    const int gg  = isC ? b - NB_GRAPHS : b;
    const float* x = isC ? xc : xq;
    const int* src = isC ? srcc : srcq;
    const int* dst = isC ? dstc : dstq;

    const int nb = gg * M_NODES;
    const int eb = gg * EPG;

    if (t < 64) scnt[t] = 0;
    __syncthreads();

    for (int e = t; e < EPG; e += 256)
        atomicAdd(&scnt[dst[eb + e] - nb], 1);
    for (int i = t; i < 64*32; i += 256) pool[i] = x[(long)nb*32 + i];
    __syncthreads();

    if (t == 0) {
        int a = 0;
        for (int i = 0; i < 64; ++i) { sstart[i] = a; a += scnt[i]; }
        sstart[64] = a;
    }
    __syncthreads();
    if (t < 64) {
        scnt[t] = sstart[t];
        sdinv[t] = rsqrtf(1.0f + (float)(sstart[t + 1] - sstart[t]));
    }
    __syncthreads();

    for (int e = t; e < EPG; e += 256) {
        int d = dst[eb + e] - nb;
        int s = src[eb + e] - nb;
        int p = atomicAdd(&scnt[d], 1);
        ssrc[p] = s;
    }
    __syncthreads();

    gcn_layer_body<32,64>(pool, pool+2048, pool+6144, sdinv, sstart, ssrc,
                          Wg0, bg0, g_scratch + (isC?OFF_FC0:OFF_FQ0) + (long)nb*64, t);
    for (int i = t; i < 64*64; i += 256) pool[i] = fmaxf(pool[6144 + i], 0.f);
    __syncthreads();

    gcn_layer_body<64,32>(pool, pool+4096, pool+6144, sdinv, sstart, ssrc,
                          Wg1, bg1, g_scratch + (isC?OFF_FC1:OFF_FQ1) + (long)nb*32, t);
    for (int i = t; i < 64*32; i += 256) pool[i] = fmaxf(pool[6144 + i], 0.f);
    __syncthreads();

    gcn_layer_body<32,16>(pool, pool+2048, pool+3072, sdinv, sstart, ssrc,
                          Wg2, bg2, g_scratch + (isC?OFF_FC2:OFF_FQ2) + (long)nb*16, t);
}

// ---------------------------------------------------------------------------
// Fused pair kernel: sim GEMM (tf32 mma) + conv0 (tf32 mma implicit GEMM,
// shuffle pool, fp16 plane output) + conv1 (f16 m16n8k16 mma, tap-paired K,
// ldmatrix A feed, shuffle pool).
//
// Dynamic smem buf (13584 floats = 54336 B); __launch_bounds__(256,4):
// 4 blocks/SM (4 x 54336 = 217KB smem, 64 regs/thread cap).
//   simh     : [0,4624)       68x68 halo sim (fp32/tf32); swh overlays in ph3
//   sq       : [4624,8976)    phase 0-1 ([m][F+4] padded)
//   scB      : [8976,13584)   phase 0-1 ([k][72])
//   planes16 : halves at buf+4624, 1296 px x 8 ch fp16 (16B/px); overlays sq/scB
// ---------------------------------------------------------------------------
__global__ void __launch_bounds__(256, 4) pair_all(
    const float* __restrict__ cw0, const float* __restrict__ cb0,
    const float* __restrict__ cw1, const float* __restrict__ cb1)
{
    extern __shared__ __align__(16) float buf[];
    __shared__ float sw0t[32*12];   // conv0 weights [k][o] stride 12, taps 25-31 zero
    __shared__ int   soff0[32];     // conv0 tap offsets in simh (68-stride)
    __shared__ int   offA16[13], offB16[13];  // conv1 tap-pair pixel offsets (bytes)

    float*  simh     = buf;                      // [0,4624)
    float*  sq       = buf + 4624;
    float*  scB      = buf + 8976;
    __half* planes_h = (__half*)(buf + 4624);    // 10368 halves used (1296 px x 8)
    __half* swh      = (__half*)buf;             // conv1 weights [kp][o16][k16] halves

    const int simi = blockIdx.x % 3;
    const int bk   = blockIdx.x / 3;
    const int lf   = 6 - simi;               // log2(F)
    const int F    = 1 << lf;                // 64, 32, 16
    const int SP   = F + 4;                  // padded sq stride
    const int offq = (simi == 0) ? OFF_FQ0 : (simi == 1) ? OFF_FQ1 : OFF_FQ2;
    const int offc = (simi == 0) ? OFF_FC0 : (simi == 1) ? OFF_FC1 : OFF_FC2;
    const float* cw0p = cw0 + simi*200;
    const float* cb0p = cb0 + simi*8;
    const float* cw1p = cw1 + simi*3200;
    const float* cb1p = cb1 + simi*16;

    const int t = threadIdx.x;
    const int warp = t >> 5, lane = t & 31, g = lane >> 2, tig = lane & 3;
    const float* fq = g_scratch + offq + ((long)bk << (6 + lf));
    const float* fc = g_scratch + offc + ((long)bk << (6 + lf));

    // ---- phase 0: stage features + conv0 weights + tap tables + simh halo ----
    for (int i = t; i < (64 << lf); i += 256) {
        int n = i >> lf, k = i & (F - 1);
        sq[n*SP + k] = fq[i];
    }
    for (int i = t; i < (64 << lf); i += 256) {
        int n = i >> lf, k = i & (F - 1);
        scB[k*72 + n] = fc[i];
    }
    {   // conv0 weights: [k][o] stride 12, zero-pad k>=25
        int k = t >> 3, o = t & 7;
        float w = (k < 25) ? __ldg(&cw0p[o*25 + k]) : 0.f;
        sw0t[k*12 + o] = tf32f(w);
        if (t < 32) soff0[t] = (t < 25) ? (t/5)*68 + (t%5) : 0;
        if (t < 13) {
            int ta = 2*t, tb = 2*t + 1;
            offA16[t] = ((ta/5)*36 + ta%5) * 16;
            offB16[t] = (tb < 25) ? ((tb/5)*36 + tb%5) * 16 : 0;
        }
    }
    // simh halo: rows {0,1,66,67} full (272) + cols {0,1,66,67} of rows 2..65 (256)
    for (int i = t; i < 528; i += 256) {
        int idx;
        if (i < 272) {
            int r = (i < 136) ? (i/68) : 66 + (i-136)/68;
            idx = r*68 + (i % 68);
        } else {
            int j = i - 272;
            int r = 2 + (j >> 2);
            int cm = j & 3;
            int c = (cm < 2) ? cm : 64 + cm;
            idx = r*68 + c;
        }
        simh[idx] = 0.f;
    }
    __syncthreads();

    // ---- phase 1: similarity GEMM on tensor cores -> simh (halo, tf32) ----
    {
        const int wm = warp & 3;
        const int n0base = (warp >> 2) * 32;
        float c[4][4];
        #pragma unroll
        for (int ni = 0; ni < 4; ++ni)
            #pragma unroll
            for (int r = 0; r < 4; ++r) c[ni][r] = 0.f;

        const int nk = F >> 3;
        for (int kk = 0; kk < nk; ++kk) {
            const float* ap = sq + (wm*16 + g)*SP + kk*8 + tig;
            unsigned a0 = __float_as_uint(ap[0]);
            unsigned a1 = __float_as_uint(ap[8*SP]);
            unsigned a2 = __float_as_uint(ap[4]);
            unsigned a3 = __float_as_uint(ap[8*SP + 4]);
            const float* bp = scB + (kk*8 + tig)*72 + n0base + g;
            #pragma unroll
            for (int ni = 0; ni < 4; ++ni) {
                unsigned b0 = __float_as_uint(bp[ni*8]);
                unsigned b1 = __float_as_uint(bp[4*72 + ni*8]);
                mma_tf32(c[ni], a0, a1, a2, a3, b0, b1);
            }
        }
        #pragma unroll
        for (int ni = 0; ni < 4; ++ni) {
            int col = n0base + ni*8 + 2*tig;
            int row = wm*16 + g;
            *(float2*)&simh[(row+2)*68 + col+2] =
                make_float2(tf32f(c[ni][0]), tf32f(c[ni][1]));
            *(float2*)&simh[(row+10)*68 + col+2] =
                make_float2(tf32f(c[ni][2]), tf32f(c[ni][3]));
        }
    }
    __syncthreads();

    // ---- phase 2a: zero planes halo pixels (16B each) ----
    for (int i = t; i < 272; i += 256) {
        int pix;
        if (i < 72)       pix = i;
        else if (i < 144) pix = 34*36 + (i - 72);
        else {
            int j = i - 144;
            int row = 2 + (j >> 2);
            int col = (j & 3); col = (col < 2) ? col : col + 32;
            pix = row*36 + col;
        }
        *(float4*)(planes_h + pix*8) = make_float4(0.f,0.f,0.f,0.f);
    }

    // ---- phase 2b: conv0 as tf32 implicit GEMM + shuffle pool -> fp16 planes ----
    {
        unsigned bw[4][2];
        #pragma unroll
        for (int kk = 0; kk < 4; ++kk) {
            bw[kk][0] = __float_as_uint(sw0t[(kk*8 + tig)*12 + g]);
            bw[kk][1] = __float_as_uint(sw0t[(kk*8 + tig + 4)*12 + g]);
        }
        const float bias01[2] = { __ldg(&cb0p[2*tig]), __ldg(&cb0p[2*tig + 1]) };

        #pragma unroll
        for (int yb = 0; yb < 4; ++yb) {
            #pragma unroll
            for (int xq = 0; xq < 4; ++xq) {
                const int y0 = warp*8 + 2*yb;
                const int x0 = xq*16;
                const float* pA = simh + y0*68 + x0;
                const float* pB = pA + 68;

                float accA[4] = {0.f,0.f,0.f,0.f};
                float accB[4] = {0.f,0.f,0.f,0.f};
                #pragma unroll
                for (int kk = 0; kk < 4; ++kk) {
                    const int klo = kk*8 + tig;
                    const int o1 = soff0[klo], o2 = soff0[klo + 4];
                    {
                        unsigned a0 = __float_as_uint(pA[o1 + g]);
                        unsigned a1 = __float_as_uint(pA[o1 + g + 8]);
                        unsigned a2 = __float_as_uint(pA[o2 + g]);
                        unsigned a3 = __float_as_uint(pA[o2 + g + 8]);
                        mma_tf32(accA, a0, a1, a2, a3, bw[kk][0], bw[kk][1]);
                    }
                    {
                        unsigned a0 = __float_as_uint(pB[o1 + g]);
                        unsigned a1 = __float_as_uint(pB[o1 + g + 8]);
                        unsigned a2 = __float_as_uint(pB[o2 + g]);
                        unsigned a3 = __float_as_uint(pB[o2 + g + 8]);
                        mma_tf32(accB, a0, a1, a2, a3, bw[kk][0], bw[kk][1]);
                    }
                }
                float ym[4], nb[4];
                #pragma unroll
                for (int r = 0; r < 4; ++r)
                    ym[r] = fmaxf(accA[r], accB[r]);
                #pragma unroll
                for (int r = 0; r < 4; ++r)
                    nb[r] = __shfl_down_sync(0xffffffffu, ym[r], 4);
                if ((g & 1) == 0) {
                    const int Y   = warp*4 + yb;
                    const int XpL = xq*8 + (g >> 1);
                    const int XpH = XpL + 4;
                    float v0L = fmaxf(fmaxf(ym[0], nb[0]) + bias01[0], 0.f);
                    float v1L = fmaxf(fmaxf(ym[1], nb[1]) + bias01[1], 0.f);
                    float v0H = fmaxf(fmaxf(ym[2], nb[2]) + bias01[0], 0.f);
                    float v1H = fmaxf(fmaxf(ym[3], nb[3]) + bias01[1], 0.f);
                    int pixL = (2 + Y)*36 + 2 + XpL;
                    int pixH = (2 + Y)*36 + 2 + XpH;
                    *(__half2*)&planes_h[pixL*8 + 2*tig] =
                        __floats2half2_rn(v0L, v1L);
                    *(__half2*)&planes_h[pixH*8 + 2*tig] =
                        __floats2half2_rn(v0H, v1H);
                }
            }
        }
    }
    __syncthreads();

    // ---- phase 3a: stage conv1 weights [kp][o16][k16] fp16 (simh dead) ----
    for (int i = t; i < 3328; i += 256) {
        int kp = i >> 8, rem = i & 255;
        int o = rem >> 4, k = rem & 15;
        int c = k & 7, tap = 2*kp + (k >> 3);
        float w = (tap < 25) ? __ldg(&cw1p[o*200 + c*25 + tap]) : 0.f;
        swh[i] = __float2half_rn(w);
    }
    __syncthreads();

    // ---- phase 3b+3c: conv1 as tap-paired f16 m16n8k16 mma, two mi-batches ----
    {
        const unsigned planes_s = (unsigned)__cvta_generic_to_shared(planes_h);
        const int rowl = (lane & 7) + ((lane >> 3) & 1) * 8;
        const bool hiK = (lane >= 16);     // lanes 16-31 feed k8-15 (tapB rows)
        float* hout = g_scratch + OFF_H + simi*4096 + (long)bk * 12288;

        #pragma unroll
        for (int b2 = 0; b2 < 2; ++b2) {
            float acc[4][2][4];
            #pragma unroll
            for (int j = 0; j < 4; ++j)
                #pragma unroll
                for (int ni = 0; ni < 2; ++ni)
                    #pragma unroll
                    for (int r = 0; r < 4; ++r) acc[j][ni][r] = 0.f;

            unsigned abase[4];
            #pragma unroll
            for (int j = 0; j < 4; ++j) {
                int mt = warp*8 + b2*4 + j;
                int pix0 = (mt >> 1)*36 + (mt & 1)*16;
                abase[j] = planes_s + (unsigned)((pix0 + rowl) * 16);
            }

            for (int kp = 0; kp < 13; ++kp) {
                const unsigned toff = (unsigned)(hiK ? offB16[kp] : offA16[kp]);
                const __half* wb = swh + kp*256;
                unsigned b00 = *(const unsigned*)&wb[g*16 + 2*tig];
                unsigned b01 = *(const unsigned*)&wb[g*16 + 2*tig + 8];
                unsigned b10 = *(const unsigned*)&wb[(g+8)*16 + 2*tig];
                unsigned b11 = *(const unsigned*)&wb[(g+8)*16 + 2*tig + 8];
                #pragma unroll
                for (int j = 0; j < 4; ++j) {
                    unsigned a0, a1, a2, a3;
                    ldsm_x4(a0, a1, a2, a3, abase[j] + toff);
                    mma_f16(acc[j][0], a0, a1, a2, a3, b00, b01);
                    mma_f16(acc[j][1], a0, a1, a2, a3, b10, b11);
                }
            }

            // pooling for this batch (h = b2): jA = xh, jB = xh+2
            #pragma unroll
            for (int xh = 0; xh < 2; ++xh) {
                #pragma unroll
                for (int ni = 0; ni < 2; ++ni) {
                    float ym[4], nb[4];
                    #pragma unroll
                    for (int r = 0; r < 4; ++r)
                        ym[r] = fmaxf(acc[xh][ni][r], acc[xh + 2][ni][r]);
                    #pragma unroll
                    for (int r = 0; r < 4; ++r)
                        nb[r] = __shfl_down_sync(0xffffffffu, ym[r], 4);
                    if ((g & 1) == 0) {
                        const int Y   = 2*warp + b2;
                        const int XpL = 8*xh + (g >> 1);
                        const int XpH = XpL + 4;
                        #pragma unroll
                        for (int cc = 0; cc < 2; ++cc) {
                            const int o = ni*8 + 2*tig + cc;
                            const float b = __ldg(&cb1p[o]);
                            float vL = fmaxf(fmaxf(ym[cc],   nb[cc])   + b, 0.f);
                            float vH = fmaxf(fmaxf(ym[2+cc], nb[2+cc]) + b, 0.f);
                            hout[o*256 + Y*16 + XpL] = tf32f(vL);
                            hout[o*256 + Y*16 + XpH] = tf32f(vH);
                        }
                    }
                }
            }
        }
    }
}

// ---------------------------------------------------------------------------
// MLP layer 0: y1 += h @ Wl0. tf32 mma, cp.async double-buffered.
// (R11-proven: split-K 16, grid (4,4,16))
// ---------------------------------------------------------------------------
#define G1_KC 768
#define G1_KT 32
#define G1_NT 24
#define AS_STRIDE 36
#define BS_STRIDE 72
#define AS_SZ (128*AS_STRIDE)
#define BS_SZ (32*BS_STRIDE)

__global__ void __launch_bounds__(256) gemm1_kernel()
{
    extern __shared__ __align__(16) float gbuf[];
    const float* A = g_scratch + OFF_H;
    const float* B = g_scratch + OFF_WT0;
    float* C = g_scratch + OFF_Y1;

    const int r0 = blockIdx.x * 128;
    const int c0 = blockIdx.y * 64;
    const int k0 = blockIdx.z * G1_KC;

    const int t = threadIdx.x, warp = t >> 5, lane = t & 31;
    const int g = lane >> 2, tig = lane & 3;
    const int wm = warp & 3, wn = warp >> 2;

    float acc[2][4][4];
    #pragma unroll
    for (int mi = 0; mi < 2; ++mi)
        #pragma unroll
        for (int ni = 0; ni < 4; ++ni)
            #pragma unroll
            for (int r = 0; r < 4; ++r) acc[mi][ni][r] = 0.f;

    auto issue = [&](int ibuf, int kt) {
        float* As = gbuf + ibuf*AS_SZ;
        float* Bs = gbuf + 2*AS_SZ + ibuf*BS_SZ;
        #pragma unroll
        for (int j = 0; j < 4; ++j) {
            int cid = t + 256*j;
            int row = cid >> 3, seg = cid & 7;
            cp_async16(&As[row*AS_STRIDE + seg*4],
                       A + (long)(r0 + row)*12288 + k0 + kt + seg*4);
        }
        #pragma unroll
        for (int j = 0; j < 2; ++j) {
            int cid = t + 256*j;
            int k = cid >> 4, seg = cid & 15;
            cp_async16(&Bs[k*BS_STRIDE + seg*4],
                       B + (long)(k0 + kt + k)*256 + c0 + seg*4);
        }
        asm volatile("cp.async.commit_group;");
    };

    issue(0, 0);
    issue(1, G1_KT);

    for (int i = 0; i < G1_NT; ++i) {
        if (i < G1_NT - 1) asm volatile("cp.async.wait_group 1;");
        else               asm volatile("cp.async.wait_group 0;");
        __syncthreads();

        const float* As = gbuf + (i & 1)*AS_SZ;
        const float* Bs = gbuf + 2*AS_SZ + (i & 1)*BS_SZ;
        #pragma unroll
        for (int kc = 0; kc < 4; ++kc) {
            unsigned af[2][4], bf[4][2];
            #pragma unroll
            for (int mi = 0; mi < 2; ++mi) {
                const float* ap = As + (wm*32 + mi*16 + g)*AS_STRIDE + kc*8 + tig;
                af[mi][0] = __float_as_uint(ap[0]);
                af[mi][1] = __float_as_uint(ap[8*AS_STRIDE]);
                af[mi][2] = __float_as_uint(ap[4]);
                af[mi][3] = __float_as_uint(ap[8*AS_STRIDE + 4]);
            }
            #pragma unroll
            for (int ni = 0; ni < 4; ++ni) {
                const float* bp = Bs + (kc*8 + tig)*BS_STRIDE + wn*32 + ni*8 + g;
                bf[ni][0] = __float_as_uint(bp[0]);
                bf[ni][1] = __float_as_uint(bp[4*BS_STRIDE]);
            }
            #pragma unroll
            for (int mi = 0; mi < 2; ++mi)
                #pragma unroll
                for (int ni = 0; ni < 4; ++ni)
                    mma_tf32(acc[mi][ni], af[mi][0], af[mi][1], af[mi][2], af[mi][3],
                             bf[ni][0], bf[ni][1]);
        }
        __syncthreads();
        if (i + 2 < G1_NT) issue(i & 1, (i + 2)*G1_KT);
    }

    #pragma unroll
    for (int mi = 0; mi < 2; ++mi) {
        int R = r0 + wm*32 + mi*16 + g;
        #pragma unroll
        for (int ni = 0; ni < 4; ++ni) {
            int Cc = c0 + wn*32 + ni*8 + 2*tig;
            atomicAdd(&C[R*256 + Cc],         acc[mi][ni][0]);
            atomicAdd(&C[R*256 + Cc + 1],     acc[mi][ni][1]);
            atomicAdd(&C[(R+8)*256 + Cc],     acc[mi][ni][2]);
            atomicAdd(&C[(R+8)*256 + Cc + 1], acc[mi][ni][3]);
        }
    }
}

// ---------------------------------------------------------------------------
// Head: split-K (4 slices of 64), 256 threads/block, one block per row.
// (R8-proven version: 15.1-15.4us)
// ---------------------------------------------------------------------------
__global__ void __launch_bounds__(256) head_kernel(
    const float* __restrict__ Wl1, const float* __restrict__ bl1,
    const float* __restrict__ Wsc, const float* __restrict__ bsc,
    float* __restrict__ out)
{
    const int r = blockIdx.x;
    const int t = threadIdx.x;
    __shared__ float sy[256];
    __shared__ float part[4][64];
    __shared__ float red[2];

    sy[t] = fmaxf(g_scratch[OFF_Y1 + (long)r*256 + t], 0.f);
    __syncthreads();

    const int j = t & 63, ks = t >> 6;
    float acc = 0.f;
    #pragma unroll 16
    for (int k = 64*ks; k < 64*ks + 64; ++k)
        acc += sy[k] * __ldg(&Wl1[k*64 + j]);
    part[ks][j] = acc;
    __syncthreads();

    if (t < 64) {
        float a = part[0][t] + part[1][t] + part[2][t] + part[3][t] + __ldg(&bl1[t]);
        float v = fmaxf(a, 0.f) * __ldg(&Wsc[t]);
        #pragma unroll
        for (int off = 16; off > 0; off >>= 1)
            v += __shfl_down_sync(0xffffffffu, v, off);
        if ((t & 31) == 0) red[t >> 5] = v;
    }
    __syncthreads();
    if (t == 0) {
        float s = red[0] + red[1] + __ldg(&bsc[0]);
        out[r] = 1.f / (1.f + expf(-s));
    }
}

// ---------------------------------------------------------------------------
// Launch
// ---------------------------------------------------------------------------
#define PAIR_SMEM (13584*4)
#define G1_SMEM ((2*AS_SZ + 2*BS_SZ)*4)

extern "C" void kernel_launch(void* const* d_in, const int* in_sizes, int n_in,
                              void* d_out, int out_size)
{
    (void)in_sizes; (void)n_in; (void)out_size;
    const float* x_q  = (const float*)d_in[0];
    const float* x_c  = (const float*)d_in[1];
    const int*   src_q = (const int*)d_in[2];
    const int*   dst_q = (const int*)d_in[3];
    const int*   src_c = (const int*)d_in[4];
    const int*   dst_c = (const int*)d_in[5];
    const float* Wg0 = (const float*)d_in[6];
    const float* bg0 = (const float*)d_in[7];
    const float* Wg1 = (const float*)d_in[8];
    const float* bg1 = (const float*)d_in[9];
    const float* Wg2 = (const float*)d_in[10];
    const float* bg2 = (const float*)d_in[11];
    const float* cw0 = (const float*)d_in[12];
    const float* cb0 = (const float*)d_in[13];
    const float* cw1 = (const float*)d_in[14];
    const float* cb1 = (const float*)d_in[15];
    const float* Wl0 = (const float*)d_in[16];
    const float* bl0 = (const float*)d_in[17];
    const float* Wl1 = (const float*)d_in[18];
    const float* bl1 = (const float*)d_in[19];
    const float* Wsc = (const float*)d_in[20];
    const float* bsc = (const float*)d_in[21];
    float* out = (float*)d_out;

    static int attr_done = 0;
    if (!attr_done) {
        cudaFuncSetAttribute(pair_all,  cudaFuncAttributeMaxDynamicSharedMemorySize, PAIR_SMEM);
        cudaFuncSetAttribute(gemm1_kernel, cudaFuncAttributeMaxDynamicSharedMemorySize, G1_SMEM);
        attr_done = 1;
    }

    // fused: 3-layer GCN (1024 blocks) + y1 bias init (512) + Wl0 tf32 (3072)
    prep_all<<<2*NB_GRAPHS + 512 + 3072, 256>>>(
        x_q, x_c, Wg0, bg0, Wg1, bg1, Wg2, bg2,
        src_q, dst_q, src_c, dst_c, bl0, Wl0);

    // fused sim + conv stacks (all 3 sims), 4 blocks/SM
    pair_all<<<3*NB_GRAPHS, 256, PAIR_SMEM>>>(cw0, cb0, cw1, cb1);

    // MLP layer 0 on tensor cores (split-K 16), then head
    gemm1_kernel<<<dim3(4, 4, 16), 256, G1_SMEM>>>();
    head_kernel<<<512, 256>>>(Wl1, bl1, Wsc, bsc, out);
}

// round 17
// speedup vs baseline: 1.0674x; 1.0674x over previous
#include <cuda_runtime.h>
#include <cuda_fp16.h>
#include <math.h>

// ---------------------------------------------------------------------------
// Problem constants
// ---------------------------------------------------------------------------
#define NB_GRAPHS 512          // B
#define M_NODES   64           // nodes per graph
#define EPG       512          // edges per graph

// ---------------------------------------------------------------------------
// Scratch layout (single __device__ array, no allocations)
// ---------------------------------------------------------------------------
#define SZ_F0 (32768*64)
#define SZ_F1 (32768*32)
#define SZ_F2 (32768*16)
#define SZ_H  (512*12288)
#define SZ_Y1 (512*256)
#define SZ_WT0 (12288*256)

#define OFF_FQ0 0
#define OFF_FC0 (OFF_FQ0 + SZ_F0)
#define OFF_FQ1 (OFF_FC0 + SZ_F0)
#define OFF_FC1 (OFF_FQ1 + SZ_F1)
#define OFF_FQ2 (OFF_FC1 + SZ_F1)
#define OFF_FC2 (OFF_FQ2 + SZ_F2)
#define OFF_H   (OFF_FC2 + SZ_F2)
#define OFF_Y1  (OFF_H + SZ_H)
#define OFF_WT0 (OFF_Y1 + SZ_Y1)
#define SCRATCH_TOTAL (OFF_WT0 + SZ_WT0)

__device__ float g_scratch[SCRATCH_TOTAL];

// ---------------------------------------------------------------------------
// Helpers
// ---------------------------------------------------------------------------
typedef unsigned long long u64;

__device__ __forceinline__ unsigned f2tf32(float f) {
    unsigned u; asm("cvt.rna.tf32.f32 %0, %1;" : "=r"(u) : "f"(f)); return u;
}
__device__ __forceinline__ float tf32f(float f) {
    return __uint_as_float(f2tf32(f));
}
__device__ __forceinline__ void cp_async16(float* dst, const float* src) {
    unsigned d = (unsigned)__cvta_generic_to_shared(dst);
    asm volatile("cp.async.cg.shared.global [%0], [%1], 16;" :: "r"(d), "l"(src));
}
__device__ __forceinline__ void mma_tf32(float c[4],
    unsigned a0, unsigned a1, unsigned a2, unsigned a3,
    unsigned b0, unsigned b1)
{
    asm volatile(
        "mma.sync.aligned.m16n8k8.row.col.f32.tf32.tf32.f32 "
        "{%0,%1,%2,%3}, {%4,%5,%6,%7}, {%8,%9}, {%0,%1,%2,%3};"
        : "+f"(c[0]), "+f"(c[1]), "+f"(c[2]), "+f"(c[3])
        : "r"(a0), "r"(a1), "r"(a2), "r"(a3), "r"(b0), "r"(b1));
}
__device__ __forceinline__ void mma_f16(float c[4],
    unsigned a0, unsigned a1, unsigned a2, unsigned a3,
    unsigned b0, unsigned b1)
{
    asm volatile(
        "mma.sync.aligned.m16n8k16.row.col.f32.f16.f16.f32 "
        "{%0,%1,%2,%3}, {%4,%5,%6,%7}, {%8,%9}, {%0,%1,%2,%3};"
        : "+f"(c[0]), "+f"(c[1]), "+f"(c[2]), "+f"(c[3])
        : "r"(a0), "r"(a1), "r"(a2), "r"(a3), "r"(b0), "r"(b1));
}
__device__ __forceinline__ void ldsm_x4(unsigned& r0, unsigned& r1,
                                        unsigned& r2, unsigned& r3, unsigned addr)
{
    asm volatile("ldmatrix.sync.aligned.m8n8.x4.shared.b16 {%0,%1,%2,%3}, [%4];"
        : "=r"(r0), "=r"(r1), "=r"(r2), "=r"(r3) : "r"(addr));
}

// ---------------------------------------------------------------------------
// GCN layer body. k-chunked GEMM (wcol[32] regs max, partial sums staged in
// sA -> low register pressure). Bit-identical accumulation order vs before.
// Feature outputs tf32-rounded.
// ---------------------------------------------------------------------------
template<int FIN, int FOUT>
__device__ __forceinline__ void gcn_layer_body(
    const float* __restrict__ sx, float* __restrict__ sA, float* __restrict__ sout,
    const float* __restrict__ sdinv,
    const int* __restrict__ sstart, const int* __restrict__ ssrc,
    const float* __restrict__ W, const float* __restrict__ bias,
    float* __restrict__ outg, int t)
{
    // GEMM: sA[n][j] = sum_k sx[n][k] * W[k][j], k chunked by 32
    #pragma unroll
    for (int kc = 0; kc < FIN; kc += 32) {
        const int j = t % FOUT;
        float wcol[32];
        #pragma unroll
        for (int kk = 0; kk < 32; ++kk)
            wcol[kk] = __ldg(&W[(kc + kk)*FOUT + j]);
        for (int i = t; i < 64*FOUT; i += 256) {
            int n = i / FOUT;
            const float4* xr = (const float4*)(sx + n*FIN + kc);
            float acc = (kc == 0) ? 0.f : sA[i];
            #pragma unroll
            for (int k4 = 0; k4 < 8; ++k4) {
                float4 xv = xr[k4];
                acc += xv.x*wcol[4*k4] + xv.y*wcol[4*k4+1]
                     + xv.z*wcol[4*k4+2] + xv.w*wcol[4*k4+3];
            }
            sA[i] = acc;
        }
    }
    // scale by dinv (same single multiply as before; own slots, no sync needed)
    for (int i = t; i < 64*FOUT; i += 256)
        sA[i] *= sdinv[i / FOUT];
    __syncthreads();

    {
        const int wp = t >> 5, lane = t & 31;
        constexpr int CH = (FOUT + 31) / 32;
        for (int d = wp; d < 64; d += 8) {
            const int e0 = sstart[d], e1 = sstart[d + 1];
            const float dv = sdinv[d];
            float a[CH];
            #pragma unroll
            for (int c = 0; c < CH; ++c) {
                int j = lane + 32*c;
                a[c] = (j < FOUT) ? sA[d*FOUT + j] : 0.f;
            }
            for (int e = e0; e < e1; ++e) {
                int s = ssrc[e];
                #pragma unroll
                for (int c = 0; c < CH; ++c) {
                    int j = lane + 32*c;
                    if (j < FOUT) a[c] += sA[s*FOUT + j];
                }
            }
            #pragma unroll
            for (int c = 0; c < CH; ++c) {
                int j = lane + 32*c;
                if (j < FOUT) sout[d*FOUT + j] = dv*a[c] + __ldg(&bias[j]);
            }
        }
    }
    __syncthreads();

    for (int i = t; i < 64*FOUT; i += 256)
        outg[i] = tf32f(sout[i]);           // tf32-rounded feature copies
}

// ---------------------------------------------------------------------------
// prep_all: [0,1024) GCN; [1024,1536) y1 bias init; [1536,4608) Wl0 tf32.
// __launch_bounds__(256,4): 4 blocks/SM (smem 43KB, regs capped 64).
// ---------------------------------------------------------------------------
__global__ void __launch_bounds__(256, 4) prep_all(
    const float* __restrict__ xq, const float* __restrict__ xc,
    const float* __restrict__ Wg0, const float* __restrict__ bg0,
    const float* __restrict__ Wg1, const float* __restrict__ bg1,
    const float* __restrict__ Wg2, const float* __restrict__ bg2,
    const int* __restrict__ srcq, const int* __restrict__ dstq,
    const int* __restrict__ srcc, const int* __restrict__ dstc,
    const float* __restrict__ bl0, const float* __restrict__ Wl0)
{
    __shared__ __align__(16) float pool[10240];
    __shared__ int   ssrc[EPG];
    __shared__ int   sstart[65];
    __shared__ int   scnt[64];
    __shared__ float sdinv[64];

    const int b = blockIdx.x;
    const int t = threadIdx.x;

    if (b >= 2*NB_GRAPHS) {
        if (b < 2*NB_GRAPHS + 512) {
            int i = (b - 2*NB_GRAPHS)*256 + t;
            g_scratch[OFF_Y1 + i] = __ldg(&bl0[i & 255]);
        } else {
            int i = (b - (2*NB_GRAPHS + 512))*256 + t;   // float4 index
            float4 v = ((const float4*)Wl0)[i];
            float4 o;
            o.x = tf32f(v.x); o.y = tf32f(v.y); o.z = tf32f(v.z); o.w = tf32f(v.w);
            ((float4*)(g_scratch + OFF_WT0))[i] = o;
        }
        return;
    }

    const bool isC = (b >= NB_GRAPHS);
    const int gg  = isC ? b - NB_GRAPHS : b;
    const float* x = isC ? xc : xq;
    const int* src = isC ? srcc : srcq;
    const int* dst = isC ? dstc : dstq;

    const int nb = gg * M_NODES;
    const int eb = gg * EPG;

    if (t < 64) scnt[t] = 0;
    __syncthreads();

    for (int e = t; e < EPG; e += 256)
        atomicAdd(&scnt[dst[eb + e] - nb], 1);
    for (int i = t; i < 64*32; i += 256) pool[i] = x[(long)nb*32 + i];
    __syncthreads();

    if (t == 0) {
        int a = 0;
        for (int i = 0; i < 64; ++i) { sstart[i] = a; a += scnt[i]; }
        sstart[64] = a;
    }
    __syncthreads();
    if (t < 64) {
        scnt[t] = sstart[t];
        sdinv[t] = rsqrtf(1.0f + (float)(sstart[t + 1] - sstart[t]));
    }
    __syncthreads();

    for (int e = t; e < EPG; e += 256) {
        int d = dst[eb + e] - nb;
        int s = src[eb + e] - nb;
        int p = atomicAdd(&scnt[d], 1);
        ssrc[p] = s;
    }
    __syncthreads();

    gcn_layer_body<32,64>(pool, pool+2048, pool+6144, sdinv, sstart, ssrc,
                          Wg0, bg0, g_scratch + (isC?OFF_FC0:OFF_FQ0) + (long)nb*64, t);
    for (int i = t; i < 64*64; i += 256) pool[i] = fmaxf(pool[6144 + i], 0.f);
    __syncthreads();

    gcn_layer_body<64,32>(pool, pool+4096, pool+6144, sdinv, sstart, ssrc,
                          Wg1, bg1, g_scratch + (isC?OFF_FC1:OFF_FQ1) + (long)nb*32, t);
    for (int i = t; i < 64*32; i += 256) pool[i] = fmaxf(pool[6144 + i], 0.f);
    __syncthreads();

    gcn_layer_body<32,16>(pool, pool+2048, pool+3072, sdinv, sstart, ssrc,
                          Wg2, bg2, g_scratch + (isC?OFF_FC2:OFF_FQ2) + (long)nb*16, t);
}

// ---------------------------------------------------------------------------
// Fused pair kernel: sim GEMM (tf32 mma) + conv0 (tf32 mma implicit GEMM,
// shuffle pool, fp16 plane output) + conv1 (f16 m16n8k16 mma, tap-paired K,
// ldmatrix A feed, shuffle pool). (R14/R15-proven, 237.5us total)
//
// Dynamic smem buf (13584 floats = 54336 B); __launch_bounds__(256,4).
//   simh     : [0,4624)       68x68 halo sim (fp32/tf32); swh overlays in ph3
//   sq       : [4624,8976)    phase 0-1 ([m][F+4] padded)
//   scB      : [8976,13584)   phase 0-1 ([k][72])
//   planes16 : halves at buf+4624, 1296 px x 8 ch fp16 (16B/px); overlays sq/scB
// ---------------------------------------------------------------------------
__global__ void __launch_bounds__(256, 4) pair_all(
    const float* __restrict__ cw0, const float* __restrict__ cb0,
    const float* __restrict__ cw1, const float* __restrict__ cb1)
{
    extern __shared__ __align__(16) float buf[];
    __shared__ float sw0t[32*12];   // conv0 weights [k][o] stride 12, taps 25-31 zero
    __shared__ int   soff0[32];     // conv0 tap offsets in simh (68-stride)
    __shared__ int   offA16[13], offB16[13];  // conv1 tap-pair pixel offsets (bytes)

    float*  simh     = buf;                      // [0,4624)
    float*  sq       = buf + 4624;
    float*  scB      = buf + 8976;
    __half* planes_h = (__half*)(buf + 4624);    // 10368 halves used (1296 px x 8)
    __half* swh      = (__half*)buf;             // conv1 weights [kp][o16][k16] halves

    const int simi = blockIdx.x % 3;
    const int bk   = blockIdx.x / 3;
    const int lf   = 6 - simi;               // log2(F)
    const int F    = 1 << lf;                // 64, 32, 16
    const int SP   = F + 4;                  // padded sq stride
    const int offq = (simi == 0) ? OFF_FQ0 : (simi == 1) ? OFF_FQ1 : OFF_FQ2;
    const int offc = (simi == 0) ? OFF_FC0 : (simi == 1) ? OFF_FC1 : OFF_FC2;
    const float* cw0p = cw0 + simi*200;
    const float* cb0p = cb0 + simi*8;
    const float* cw1p = cw1 + simi*3200;
    const float* cb1p = cb1 + simi*16;

    const int t = threadIdx.x;
    const int warp = t >> 5, lane = t & 31, g = lane >> 2, tig = lane & 3;
    const float* fq = g_scratch + offq + ((long)bk << (6 + lf));
    const float* fc = g_scratch + offc + ((long)bk << (6 + lf));

    // ---- phase 0: stage features + conv0 weights + tap tables + simh halo ----
    for (int i = t; i < (64 << lf); i += 256) {
        int n = i >> lf, k = i & (F - 1);
        sq[n*SP + k] = fq[i];
    }
    for (int i = t; i < (64 << lf); i += 256) {
        int n = i >> lf, k = i & (F - 1);
        scB[k*72 + n] = fc[i];
    }
    {   // conv0 weights: [k][o] stride 12, zero-pad k>=25
        int k = t >> 3, o = t & 7;
        float w = (k < 25) ? __ldg(&cw0p[o*25 + k]) : 0.f;
        sw0t[k*12 + o] = tf32f(w);
        if (t < 32) soff0[t] = (t < 25) ? (t/5)*68 + (t%5) : 0;
        if (t < 13) {
            int ta = 2*t, tb = 2*t + 1;
            offA16[t] = ((ta/5)*36 + ta%5) * 16;
            offB16[t] = (tb < 25) ? ((tb/5)*36 + tb%5) * 16 : 0;
        }
    }
    // simh halo: rows {0,1,66,67} full (272) + cols {0,1,66,67} of rows 2..65 (256)
    for (int i = t; i < 528; i += 256) {
        int idx;
        if (i < 272) {
            int r = (i < 136) ? (i/68) : 66 + (i-136)/68;
            idx = r*68 + (i % 68);
        } else {
            int j = i - 272;
            int r = 2 + (j >> 2);
            int cm = j & 3;
            int c = (cm < 2) ? cm : 64 + cm;
            idx = r*68 + c;
        }
        simh[idx] = 0.f;
    }
    __syncthreads();

    // ---- phase 1: similarity GEMM on tensor cores -> simh (halo, tf32) ----
    {
        const int wm = warp & 3;
        const int n0base = (warp >> 2) * 32;
        float c[4][4];
        #pragma unroll
        for (int ni = 0; ni < 4; ++ni)
            #pragma unroll
            for (int r = 0; r < 4; ++r) c[ni][r] = 0.f;

        const int nk = F >> 3;
        for (int kk = 0; kk < nk; ++kk) {
            const float* ap = sq + (wm*16 + g)*SP + kk*8 + tig;
            unsigned a0 = __float_as_uint(ap[0]);
            unsigned a1 = __float_as_uint(ap[8*SP]);
            unsigned a2 = __float_as_uint(ap[4]);
            unsigned a3 = __float_as_uint(ap[8*SP + 4]);
            const float* bp = scB + (kk*8 + tig)*72 + n0base + g;
            #pragma unroll
            for (int ni = 0; ni < 4; ++ni) {
                unsigned b0 = __float_as_uint(bp[ni*8]);
                unsigned b1 = __float_as_uint(bp[4*72 + ni*8]);
                mma_tf32(c[ni], a0, a1, a2, a3, b0, b1);
            }
        }
        #pragma unroll
        for (int ni = 0; ni < 4; ++ni) {
            int col = n0base + ni*8 + 2*tig;
            int row = wm*16 + g;
            *(float2*)&simh[(row+2)*68 + col+2] =
                make_float2(tf32f(c[ni][0]), tf32f(c[ni][1]));
            *(float2*)&simh[(row+10)*68 + col+2] =
                make_float2(tf32f(c[ni][2]), tf32f(c[ni][3]));
        }
    }
    __syncthreads();

    // ---- phase 2a: zero planes halo pixels (16B each) ----
    for (int i = t; i < 272; i += 256) {
        int pix;
        if (i < 72)       pix = i;
        else if (i < 144) pix = 34*36 + (i - 72);
        else {
            int j = i - 144;
            int row = 2 + (j >> 2);
            int col = (j & 3); col = (col < 2) ? col : col + 32;
            pix = row*36 + col;
        }
        *(float4*)(planes_h + pix*8) = make_float4(0.f,0.f,0.f,0.f);
    }

    // ---- phase 2b: conv0 as tf32 implicit GEMM + shuffle pool -> fp16 planes ----
    {
        unsigned bw[4][2];
        #pragma unroll
        for (int kk = 0; kk < 4; ++kk) {
            bw[kk][0] = __float_as_uint(sw0t[(kk*8 + tig)*12 + g]);
            bw[kk][1] = __float_as_uint(sw0t[(kk*8 + tig + 4)*12 + g]);
        }
        const float bias01[2] = { __ldg(&cb0p[2*tig]), __ldg(&cb0p[2*tig + 1]) };

        #pragma unroll
        for (int yb = 0; yb < 4; ++yb) {
            #pragma unroll
            for (int xq = 0; xq < 4; ++xq) {
                const int y0 = warp*8 + 2*yb;
                const int x0 = xq*16;
                const float* pA = simh + y0*68 + x0;
                const float* pB = pA + 68;

                float accA[4] = {0.f,0.f,0.f,0.f};
                float accB[4] = {0.f,0.f,0.f,0.f};
                #pragma unroll
                for (int kk = 0; kk < 4; ++kk) {
                    const int klo = kk*8 + tig;
                    const int o1 = soff0[klo], o2 = soff0[klo + 4];
                    {
                        unsigned a0 = __float_as_uint(pA[o1 + g]);
                        unsigned a1 = __float_as_uint(pA[o1 + g + 8]);
                        unsigned a2 = __float_as_uint(pA[o2 + g]);
                        unsigned a3 = __float_as_uint(pA[o2 + g + 8]);
                        mma_tf32(accA, a0, a1, a2, a3, bw[kk][0], bw[kk][1]);
                    }
                    {
                        unsigned a0 = __float_as_uint(pB[o1 + g]);
                        unsigned a1 = __float_as_uint(pB[o1 + g + 8]);
                        unsigned a2 = __float_as_uint(pB[o2 + g]);
                        unsigned a3 = __float_as_uint(pB[o2 + g + 8]);
                        mma_tf32(accB, a0, a1, a2, a3, bw[kk][0], bw[kk][1]);
                    }
                }
                float ym[4], nb[4];
                #pragma unroll
                for (int r = 0; r < 4; ++r)
                    ym[r] = fmaxf(accA[r], accB[r]);
                #pragma unroll
                for (int r = 0; r < 4; ++r)
                    nb[r] = __shfl_down_sync(0xffffffffu, ym[r], 4);
                if ((g & 1) == 0) {
                    const int Y   = warp*4 + yb;
                    const int XpL = xq*8 + (g >> 1);
                    const int XpH = XpL + 4;
                    float v0L = fmaxf(fmaxf(ym[0], nb[0]) + bias01[0], 0.f);
                    float v1L = fmaxf(fmaxf(ym[1], nb[1]) + bias01[1], 0.f);
                    float v0H = fmaxf(fmaxf(ym[2], nb[2]) + bias01[0], 0.f);
                    float v1H = fmaxf(fmaxf(ym[3], nb[3]) + bias01[1], 0.f);
                    int pixL = (2 + Y)*36 + 2 + XpL;
                    int pixH = (2 + Y)*36 + 2 + XpH;
                    *(__half2*)&planes_h[pixL*8 + 2*tig] =
                        __floats2half2_rn(v0L, v1L);
                    *(__half2*)&planes_h[pixH*8 + 2*tig] =
                        __floats2half2_rn(v0H, v1H);
                }
            }
        }
    }
    __syncthreads();

    // ---- phase 3a: stage conv1 weights [kp][o16][k16] fp16 (simh dead) ----
    for (int i = t; i < 3328; i += 256) {
        int kp = i >> 8, rem = i & 255;
        int o = rem >> 4, k = rem & 15;
        int c = k & 7, tap = 2*kp + (k >> 3);
        float w = (tap < 25) ? __ldg(&cw1p[o*200 + c*25 + tap]) : 0.f;
        swh[i] = __float2half_rn(w);
    }
    __syncthreads();

    // ---- phase 3b+3c: conv1 as tap-paired f16 m16n8k16 mma, two mi-batches ----
    {
        const unsigned planes_s = (unsigned)__cvta_generic_to_shared(planes_h);
        const int rowl = (lane & 7) + ((lane >> 3) & 1) * 8;
        const bool hiK = (lane >= 16);     // lanes 16-31 feed k8-15 (tapB rows)
        float* hout = g_scratch + OFF_H + simi*4096 + (long)bk * 12288;

        #pragma unroll
        for (int b2 = 0; b2 < 2; ++b2) {
            float acc[4][2][4];
            #pragma unroll
            for (int j = 0; j < 4; ++j)
                #pragma unroll
                for (int ni = 0; ni < 2; ++ni)
                    #pragma unroll
                    for (int r = 0; r < 4; ++r) acc[j][ni][r] = 0.f;

            unsigned abase[4];
            #pragma unroll
            for (int j = 0; j < 4; ++j) {
                int mt = warp*8 + b2*4 + j;
                int pix0 = (mt >> 1)*36 + (mt & 1)*16;
                abase[j] = planes_s + (unsigned)((pix0 + rowl) * 16);
            }

            for (int kp = 0; kp < 13; ++kp) {
                const unsigned toff = (unsigned)(hiK ? offB16[kp] : offA16[kp]);
                const __half* wb = swh + kp*256;
                unsigned b00 = *(const unsigned*)&wb[g*16 + 2*tig];
                unsigned b01 = *(const unsigned*)&wb[g*16 + 2*tig + 8];
                unsigned b10 = *(const unsigned*)&wb[(g+8)*16 + 2*tig];
                unsigned b11 = *(const unsigned*)&wb[(g+8)*16 + 2*tig + 8];
                #pragma unroll
                for (int j = 0; j < 4; ++j) {
                    unsigned a0, a1, a2, a3;
                    ldsm_x4(a0, a1, a2, a3, abase[j] + toff);
                    mma_f16(acc[j][0], a0, a1, a2, a3, b00, b01);
                    mma_f16(acc[j][1], a0, a1, a2, a3, b10, b11);
                }
            }

            // pooling for this batch (h = b2): jA = xh, jB = xh+2
            #pragma unroll
            for (int xh = 0; xh < 2; ++xh) {
                #pragma unroll
                for (int ni = 0; ni < 2; ++ni) {
                    float ym[4], nb[4];
                    #pragma unroll
                    for (int r = 0; r < 4; ++r)
                        ym[r] = fmaxf(acc[xh][ni][r], acc[xh + 2][ni][r]);
                    #pragma unroll
                    for (int r = 0; r < 4; ++r)
                        nb[r] = __shfl_down_sync(0xffffffffu, ym[r], 4);
                    if ((g & 1) == 0) {
                        const int Y   = 2*warp + b2;
                        const int XpL = 8*xh + (g >> 1);
                        const int XpH = XpL + 4;
                        #pragma unroll
                        for (int cc = 0; cc < 2; ++cc) {
                            const int o = ni*8 + 2*tig + cc;
                            const float b = __ldg(&cb1p[o]);
                            float vL = fmaxf(fmaxf(ym[cc],   nb[cc])   + b, 0.f);
                            float vH = fmaxf(fmaxf(ym[2+cc], nb[2+cc]) + b, 0.f);
                            hout[o*256 + Y*16 + XpL] = tf32f(vL);
                            hout[o*256 + Y*16 + XpH] = tf32f(vH);
                        }
                    }
                }
            }
        }
    }
}

// ---------------------------------------------------------------------------
// MLP layer 0: y1 += h @ Wl0. tf32 mma, cp.async double-buffered.
// (R11-proven: split-K 16, grid (4,4,16))
// ---------------------------------------------------------------------------
#define G1_KC 768
#define G1_KT 32
#define G1_NT 24
#define AS_STRIDE 36
#define BS_STRIDE 72
#define AS_SZ (128*AS_STRIDE)
#define BS_SZ (32*BS_STRIDE)

__global__ void __launch_bounds__(256) gemm1_kernel()
{
    extern __shared__ __align__(16) float gbuf[];
    const float* A = g_scratch + OFF_H;
    const float* B = g_scratch + OFF_WT0;
    float* C = g_scratch + OFF_Y1;

    const int r0 = blockIdx.x * 128;
    const int c0 = blockIdx.y * 64;
    const int k0 = blockIdx.z * G1_KC;

    const int t = threadIdx.x, warp = t >> 5, lane = t & 31;
    const int g = lane >> 2, tig = lane & 3;
    const int wm = warp & 3, wn = warp >> 2;

    float acc[2][4][4];
    #pragma unroll
    for (int mi = 0; mi < 2; ++mi)
        #pragma unroll
        for (int ni = 0; ni < 4; ++ni)
            #pragma unroll
            for (int r = 0; r < 4; ++r) acc[mi][ni][r] = 0.f;

    auto issue = [&](int ibuf, int kt) {
        float* As = gbuf + ibuf*AS_SZ;
        float* Bs = gbuf + 2*AS_SZ + ibuf*BS_SZ;
        #pragma unroll
        for (int j = 0; j < 4; ++j) {
            int cid = t + 256*j;
            int row = cid >> 3, seg = cid & 7;
            cp_async16(&As[row*AS_STRIDE + seg*4],
                       A + (long)(r0 + row)*12288 + k0 + kt + seg*4);
        }
        #pragma unroll
        for (int j = 0; j < 2; ++j) {
            int cid = t + 256*j;
            int k = cid >> 4, seg = cid & 15;
            cp_async16(&Bs[k*BS_STRIDE + seg*4],
                       B + (long)(k0 + kt + k)*256 + c0 + seg*4);
        }
        asm volatile("cp.async.commit_group;");
    };

    issue(0, 0);
    issue(1, G1_KT);

    for (int i = 0; i < G1_NT; ++i) {
        if (i < G1_NT - 1) asm volatile("cp.async.wait_group 1;");
        else               asm volatile("cp.async.wait_group 0;");
        __syncthreads();

        const float* As = gbuf + (i & 1)*AS_SZ;
        const float* Bs = gbuf + 2*AS_SZ + (i & 1)*BS_SZ;
        #pragma unroll
        for (int kc = 0; kc < 4; ++kc) {
            unsigned af[2][4], bf[4][2];
            #pragma unroll
            for (int mi = 0; mi < 2; ++mi) {
                const float* ap = As + (wm*32 + mi*16 + g)*AS_STRIDE + kc*8 + tig;
                af[mi][0] = __float_as_uint(ap[0]);
                af[mi][1] = __float_as_uint(ap[8*AS_STRIDE]);
                af[mi][2] = __float_as_uint(ap[4]);
                af[mi][3] = __float_as_uint(ap[8*AS_STRIDE + 4]);
            }
            #pragma unroll
            for (int ni = 0; ni < 4; ++ni) {
                const float* bp = Bs + (kc*8 + tig)*BS_STRIDE + wn*32 + ni*8 + g;
                bf[ni][0] = __float_as_uint(bp[0]);
                bf[ni][1] = __float_as_uint(bp[4*BS_STRIDE]);
            }
            #pragma unroll
            for (int mi = 0; mi < 2; ++mi)
                #pragma unroll
                for (int ni = 0; ni < 4; ++ni)
                    mma_tf32(acc[mi][ni], af[mi][0], af[mi][1], af[mi][2], af[mi][3],
                             bf[ni][0], bf[ni][1]);
        }
        __syncthreads();
        if (i + 2 < G1_NT) issue(i & 1, (i + 2)*G1_KT);
    }

    #pragma unroll
    for (int mi = 0; mi < 2; ++mi) {
        int R = r0 + wm*32 + mi*16 + g;
        #pragma unroll
        for (int ni = 0; ni < 4; ++ni) {
            int Cc = c0 + wn*32 + ni*8 + 2*tig;
            atomicAdd(&C[R*256 + Cc],         acc[mi][ni][0]);
            atomicAdd(&C[R*256 + Cc + 1],     acc[mi][ni][1]);
            atomicAdd(&C[(R+8)*256 + Cc],     acc[mi][ni][2]);
            atomicAdd(&C[(R+8)*256 + Cc + 1], acc[mi][ni][3]);
        }
    }
}

// ---------------------------------------------------------------------------
// Head: split-K (4 slices of 64), 256 threads/block, one block per row.
// (R8-proven version: 15.1-15.4us)
// ---------------------------------------------------------------------------
__global__ void __launch_bounds__(256) head_kernel(
    const float* __restrict__ Wl1, const float* __restrict__ bl1,
    const float* __restrict__ Wsc, const float* __restrict__ bsc,
    float* __restrict__ out)
{
    const int r = blockIdx.x;
    const int t = threadIdx.x;
    __shared__ float sy[256];
    __shared__ float part[4][64];
    __shared__ float red[2];

    sy[t] = fmaxf(g_scratch[OFF_Y1 + (long)r*256 + t], 0.f);
    __syncthreads();

    const int j = t & 63, ks = t >> 6;
    float acc = 0.f;
    #pragma unroll 16
    for (int k = 64*ks; k < 64*ks + 64; ++k)
        acc += sy[k] * __ldg(&Wl1[k*64 + j]);
    part[ks][j] = acc;
    __syncthreads();

    if (t < 64) {
        float a = part[0][t] + part[1][t] + part[2][t] + part[3][t] + __ldg(&bl1[t]);
        float v = fmaxf(a, 0.f) * __ldg(&Wsc[t]);
        #pragma unroll
        for (int off = 16; off > 0; off >>= 1)
            v += __shfl_down_sync(0xffffffffu, v, off);
        if ((t & 31) == 0) red[t >> 5] = v;
    }
    __syncthreads();
    if (t == 0) {
        float s = red[0] + red[1] + __ldg(&bsc[0]);
        out[r] = 1.f / (1.f + expf(-s));
    }
}

// ---------------------------------------------------------------------------
// Launch
// ---------------------------------------------------------------------------
#define PAIR_SMEM (13584*4)
#define G1_SMEM ((2*AS_SZ + 2*BS_SZ)*4)

extern "C" void kernel_launch(void* const* d_in, const int* in_sizes, int n_in,
                              void* d_out, int out_size)
{
    (void)in_sizes; (void)n_in; (void)out_size;
    const float* x_q  = (const float*)d_in[0];
    const float* x_c  = (const float*)d_in[1];
    const int*   src_q = (const int*)d_in[2];
    const int*   dst_q = (const int*)d_in[3];
    const int*   src_c = (const int*)d_in[4];
    const int*   dst_c = (const int*)d_in[5];
    const float* Wg0 = (const float*)d_in[6];
    const float* bg0 = (const float*)d_in[7];
    const float* Wg1 = (const float*)d_in[8];
    const float* bg1 = (const float*)d_in[9];
    const float* Wg2 = (const float*)d_in[10];
    const float* bg2 = (const float*)d_in[11];
    const float* cw0 = (const float*)d_in[12];
    const float* cb0 = (const float*)d_in[13];
    const float* cw1 = (const float*)d_in[14];
    const float* cb1 = (const float*)d_in[15];
    const float* Wl0 = (const float*)d_in[16];
    const float* bl0 = (const float*)d_in[17];
    const float* Wl1 = (const float*)d_in[18];
    const float* bl1 = (const float*)d_in[19];
    const float* Wsc = (const float*)d_in[20];
    const float* bsc = (const float*)d_in[21];
    float* out = (float*)d_out;

    static int attr_done = 0;
    if (!attr_done) {
        cudaFuncSetAttribute(pair_all,  cudaFuncAttributeMaxDynamicSharedMemorySize, PAIR_SMEM);
        cudaFuncSetAttribute(gemm1_kernel, cudaFuncAttributeMaxDynamicSharedMemorySize, G1_SMEM);
        attr_done = 1;
    }

    // fused: 3-layer GCN (1024 blocks) + y1 bias init (512) + Wl0 tf32 (3072)
    prep_all<<<2*NB_GRAPHS + 512 + 3072, 256>>>(
        x_q, x_c, Wg0, bg0, Wg1, bg1, Wg2, bg2,
        src_q, dst_q, src_c, dst_c, bl0, Wl0);

    // fused sim + conv stacks (all 3 sims), 4 blocks/SM
    pair_all<<<3*NB_GRAPHS, 256, PAIR_SMEM>>>(cw0, cb0, cw1, cb1);

    // MLP layer 0 on tensor cores (split-K 16), then head
    gemm1_kernel<<<dim3(4, 4, 16), 256, G1_SMEM>>>();
    head_kernel<<<512, 256>>>(Wl1, bl1, Wsc, bsc, out);
}